// round 5
// baseline (speedup 1.0000x reference)
#include <cuda_runtime.h>
#include <math.h>

#define B_ 4
#define N_ 4096
#define M_ 4095
#define C_ 256
#define D_ 128

// Scratch (device globals; no allocation allowed)
__device__ float g_theta[B_ * N_ * D_];
__device__ float g_phi[B_ * N_ * D_];
__device__ float g_gv[B_ * N_ * D_];
__device__ float g_y[B_ * N_ * D_];

// ---------------------------------------------------------------------------
// Kernel 1: projections  out[m][n] = sum_k x[m][k] * W[k][n]
// M=16384, K=256, Nout=128. blockIdx.z selects (Wt->theta, Wp->phi, Wg->g).
// 64x64 output tile per block, 256 threads, 4x4 micro-tile per thread.
// ---------------------------------------------------------------------------
__global__ __launch_bounds__(256) void proj_kernel(
    const float* __restrict__ x, const float* __restrict__ Wt,
    const float* __restrict__ Wp, const float* __restrict__ Wg) {
  __shared__ float As[64 * 36];  // [m][k], BK=32 (+4 pad)
  __shared__ float Bs[64 * 36];  // [n][k] (transposed)

  const float* W;
  float* out;
  if (blockIdx.z == 0)      { W = Wt; out = g_theta; }
  else if (blockIdx.z == 1) { W = Wp; out = g_phi; }
  else                      { W = Wg; out = g_gv; }

  const int m0 = blockIdx.y * 64;
  const int n0 = blockIdx.x * 64;
  const int tid = threadIdx.x;
  const int tx = tid & 15, ty = tid >> 4;

  float acc[4][4];
#pragma unroll
  for (int r = 0; r < 4; r++)
#pragma unroll
    for (int c = 0; c < 4; c++) acc[r][c] = 0.0f;

  for (int k0 = 0; k0 < C_; k0 += 32) {
    {  // A tile: 64 rows x 32 cols
      int row = tid >> 3;
      int c4 = tid & 7;
      float4 v0 = *(const float4*)(x + (size_t)(m0 + row) * C_ + k0 + c4 * 4);
      *(float4*)(As + row * 36 + c4 * 4) = v0;
      float4 v1 = *(const float4*)(x + (size_t)(m0 + row + 32) * C_ + k0 + c4 * 4);
      *(float4*)(As + (row + 32) * 36 + c4 * 4) = v1;
    }
    {  // B tile: W rows k0..k0+31, cols n0..n0+63 -> Bs[n][k]
      int kr = tid >> 4;
      int c4 = tid & 15;
      float4 v0 = *(const float4*)(W + (size_t)(k0 + kr) * D_ + n0 + c4 * 4);
      Bs[(c4 * 4 + 0) * 36 + kr] = v0.x;
      Bs[(c4 * 4 + 1) * 36 + kr] = v0.y;
      Bs[(c4 * 4 + 2) * 36 + kr] = v0.z;
      Bs[(c4 * 4 + 3) * 36 + kr] = v0.w;
      float4 v1 = *(const float4*)(W + (size_t)(k0 + kr + 16) * D_ + n0 + c4 * 4);
      Bs[(c4 * 4 + 0) * 36 + kr + 16] = v1.x;
      Bs[(c4 * 4 + 1) * 36 + kr + 16] = v1.y;
      Bs[(c4 * 4 + 2) * 36 + kr + 16] = v1.z;
      Bs[(c4 * 4 + 3) * 36 + kr + 16] = v1.w;
    }
    __syncthreads();
#pragma unroll
    for (int kk = 0; kk < 32; kk += 4) {
      float4 a[4], b[4];
#pragma unroll
      for (int r = 0; r < 4; r++) a[r] = *(float4*)(As + (ty * 4 + r) * 36 + kk);
#pragma unroll
      for (int c = 0; c < 4; c++) b[c] = *(float4*)(Bs + (tx + 16 * c) * 36 + kk);
#pragma unroll
      for (int r = 0; r < 4; r++)
#pragma unroll
        for (int c = 0; c < 4; c++)
          acc[r][c] += a[r].x * b[c].x + a[r].y * b[c].y + a[r].z * b[c].z + a[r].w * b[c].w;
    }
    __syncthreads();
  }
#pragma unroll
  for (int r = 0; r < 4; r++)
#pragma unroll
    for (int c = 0; c < 4; c++)
      out[(size_t)(m0 + ty * 4 + r) * D_ + n0 + tx + 16 * c] = acc[r][c];
}

// ---------------------------------------------------------------------------
// Kernel 2: fused pooled flash attention.
// Per block: 64 queries x all 4095 pooled keys. Maxpool(2,1) fused into K/V
// tile loads. Online softmax, O in registers.
// ---------------------------------------------------------------------------
__global__ __launch_bounds__(256) void attn_kernel() {
  extern __shared__ float sm[];
  float* Qs = sm;                  // [64][132]
  float* Ks = sm + 64 * 132;       // [64][132]  pooled phi
  float* Vs = sm + 2 * 64 * 132;   // [64][132]  pooled g
  float* Ps = sm + 3 * 64 * 132;   // [64][68]

  const int b = blockIdx.y;
  const int q0 = blockIdx.x * 64;
  const float* th = g_theta + (size_t)b * N_ * D_;
  const float* ph = g_phi + (size_t)b * N_ * D_;
  const float* gv = g_gv + (size_t)b * N_ * D_;
  const int tid = threadIdx.x;
  const int tx = tid & 15, ty = tid >> 4;

  // Load Q tile once
  for (int i = tid; i < 64 * 32; i += 256) {
    int row = i >> 5, c4 = i & 31;
    *(float4*)(Qs + row * 132 + c4 * 4) =
        *(const float4*)(th + (size_t)(q0 + row) * D_ + c4 * 4);
  }

  float m_i[4], l_i[4], O[4][8];
#pragma unroll
  for (int r = 0; r < 4; r++) {
    m_i[r] = -INFINITY;
    l_i[r] = 0.0f;
#pragma unroll
    for (int c = 0; c < 8; c++) O[r][c] = 0.0f;
  }

  for (int kt = 0; kt < 64; kt++) {
    const int k0 = kt * 64;
    const int nk = min(64, M_ - k0);

    __syncthreads();  // protect Ks/Vs/Ps against previous iteration's readers
    // Load + pool K,V tiles: pooled[m] = max(row m, row m+1); m+1 <= N_-1 valid.
    for (int i = tid; i < 64 * 32; i += 256) {
      int row = i >> 5, c4 = i & 31;
      if (row < nk) {
        const float* p0 = ph + (size_t)(k0 + row) * D_ + c4 * 4;
        float4 a = *(const float4*)p0;
        float4 b2 = *(const float4*)(p0 + D_);
        float4 r4 = make_float4(fmaxf(a.x, b2.x), fmaxf(a.y, b2.y),
                                fmaxf(a.z, b2.z), fmaxf(a.w, b2.w));
        *(float4*)(Ks + row * 132 + c4 * 4) = r4;
        const float* g0 = gv + (size_t)(k0 + row) * D_ + c4 * 4;
        a = *(const float4*)g0;
        b2 = *(const float4*)(g0 + D_);
        r4 = make_float4(fmaxf(a.x, b2.x), fmaxf(a.y, b2.y),
                         fmaxf(a.z, b2.z), fmaxf(a.w, b2.w));
        *(float4*)(Vs + row * 132 + c4 * 4) = r4;
      } else {
        float4 z4 = make_float4(0.f, 0.f, 0.f, 0.f);
        *(float4*)(Ks + row * 132 + c4 * 4) = z4;
        *(float4*)(Vs + row * 132 + c4 * 4) = z4;
      }
    }
    __syncthreads();

    // S = Q . K^T ; thread owns rows 4ty+r, cols tx+16c
    float acc[4][4];
#pragma unroll
    for (int r = 0; r < 4; r++)
#pragma unroll
      for (int c = 0; c < 4; c++) acc[r][c] = 0.0f;

#pragma unroll 8
    for (int d4 = 0; d4 < 32; d4++) {
      float4 qv[4], kv[4];
#pragma unroll
      for (int r = 0; r < 4; r++) qv[r] = *(float4*)(Qs + (ty * 4 + r) * 132 + d4 * 4);
#pragma unroll
      for (int c = 0; c < 4; c++) kv[c] = *(float4*)(Ks + (tx + 16 * c) * 132 + d4 * 4);
#pragma unroll
      for (int r = 0; r < 4; r++)
#pragma unroll
        for (int c = 0; c < 4; c++)
          acc[r][c] += qv[r].x * kv[c].x + qv[r].y * kv[c].y +
                       qv[r].z * kv[c].z + qv[r].w * kv[c].w;
    }

    if (nk < 64) {
#pragma unroll
      for (int c = 0; c < 4; c++)
        if (tx + 16 * c >= nk)
#pragma unroll
          for (int r = 0; r < 4; r++) acc[r][c] = -INFINITY;
    }

    // Online softmax update (per row, reduced across the 16-lane tx group)
#pragma unroll
    for (int r = 0; r < 4; r++) {
      float mr = fmaxf(fmaxf(acc[r][0], acc[r][1]), fmaxf(acc[r][2], acc[r][3]));
#pragma unroll
      for (int off = 1; off < 16; off <<= 1)
        mr = fmaxf(mr, __shfl_xor_sync(0xffffffffu, mr, off));
      float mn = fmaxf(m_i[r], mr);
      float sc = __expf(m_i[r] - mn);
      m_i[r] = mn;
      float p0 = __expf(acc[r][0] - mn);
      float p1 = __expf(acc[r][1] - mn);
      float p2 = __expf(acc[r][2] - mn);
      float p3 = __expf(acc[r][3] - mn);
      float sr = p0 + p1 + p2 + p3;
#pragma unroll
      for (int off = 1; off < 16; off <<= 1)
        sr += __shfl_xor_sync(0xffffffffu, sr, off);
      l_i[r] = l_i[r] * sc + sr;
#pragma unroll
      for (int c = 0; c < 8; c++) O[r][c] *= sc;
      int rowp = (ty * 4 + r) * 68;
      Ps[rowp + tx] = p0;
      Ps[rowp + tx + 16] = p1;
      Ps[rowp + tx + 32] = p2;
      Ps[rowp + tx + 48] = p3;
    }
    __syncthreads();

    // O += P . V ; thread owns rows 4ty+r, dims tx*8..tx*8+7
#pragma unroll 4
    for (int j = 0; j < 64; j++) {
      float pj[4];
#pragma unroll
      for (int r = 0; r < 4; r++) pj[r] = Ps[(ty * 4 + r) * 68 + j];
      float4 v0 = *(float4*)(Vs + j * 132 + tx * 8);
      float4 v1 = *(float4*)(Vs + j * 132 + tx * 8 + 4);
#pragma unroll
      for (int r = 0; r < 4; r++) {
        O[r][0] += pj[r] * v0.x;
        O[r][1] += pj[r] * v0.y;
        O[r][2] += pj[r] * v0.z;
        O[r][3] += pj[r] * v0.w;
        O[r][4] += pj[r] * v1.x;
        O[r][5] += pj[r] * v1.y;
        O[r][6] += pj[r] * v1.z;
        O[r][7] += pj[r] * v1.w;
      }
    }
  }

  // Normalize and store y
  float* yb = g_y + (size_t)b * N_ * D_;
#pragma unroll
  for (int r = 0; r < 4; r++) {
    float inv = 1.0f / l_i[r];
    size_t base = (size_t)(q0 + ty * 4 + r) * D_ + tx * 8;
    float4 o0 = make_float4(O[r][0] * inv, O[r][1] * inv, O[r][2] * inv, O[r][3] * inv);
    float4 o1 = make_float4(O[r][4] * inv, O[r][5] * inv, O[r][6] * inv, O[r][7] * inv);
    *(float4*)(yb + base) = o0;
    *(float4*)(yb + base + 4) = o1;
  }
}

// ---------------------------------------------------------------------------
// Kernel 3: z = x + y @ Wf.  M=16384, K=128, Nout=256.
// ---------------------------------------------------------------------------
__global__ __launch_bounds__(256) void zout_kernel(const float* __restrict__ x,
                                                   const float* __restrict__ Wf,
                                                   float* __restrict__ z) {
  __shared__ float As[64 * 36];
  __shared__ float Bs[64 * 36];

  const int m0 = blockIdx.y * 64;
  const int n0 = blockIdx.x * 64;
  const int tid = threadIdx.x;
  const int tx = tid & 15, ty = tid >> 4;

  float acc[4][4];
#pragma unroll
  for (int r = 0; r < 4; r++)
#pragma unroll
    for (int c = 0; c < 4; c++) acc[r][c] = 0.0f;

  for (int k0 = 0; k0 < D_; k0 += 32) {
    {
      int row = tid >> 3;
      int c4 = tid & 7;
      float4 v0 = *(const float4*)(g_y + (size_t)(m0 + row) * D_ + k0 + c4 * 4);
      *(float4*)(As + row * 36 + c4 * 4) = v0;
      float4 v1 = *(const float4*)(g_y + (size_t)(m0 + row + 32) * D_ + k0 + c4 * 4);
      *(float4*)(As + (row + 32) * 36 + c4 * 4) = v1;
    }
    {
      int kr = tid >> 4;
      int c4 = tid & 15;
      float4 v0 = *(const float4*)(Wf + (size_t)(k0 + kr) * C_ + n0 + c4 * 4);
      Bs[(c4 * 4 + 0) * 36 + kr] = v0.x;
      Bs[(c4 * 4 + 1) * 36 + kr] = v0.y;
      Bs[(c4 * 4 + 2) * 36 + kr] = v0.z;
      Bs[(c4 * 4 + 3) * 36 + kr] = v0.w;
      float4 v1 = *(const float4*)(Wf + (size_t)(k0 + kr + 16) * C_ + n0 + c4 * 4);
      Bs[(c4 * 4 + 0) * 36 + kr + 16] = v1.x;
      Bs[(c4 * 4 + 1) * 36 + kr + 16] = v1.y;
      Bs[(c4 * 4 + 2) * 36 + kr + 16] = v1.z;
      Bs[(c4 * 4 + 3) * 36 + kr + 16] = v1.w;
    }
    __syncthreads();
#pragma unroll
    for (int kk = 0; kk < 32; kk += 4) {
      float4 a[4], b[4];
#pragma unroll
      for (int r = 0; r < 4; r++) a[r] = *(float4*)(As + (ty * 4 + r) * 36 + kk);
#pragma unroll
      for (int c = 0; c < 4; c++) b[c] = *(float4*)(Bs + (tx + 16 * c) * 36 + kk);
#pragma unroll
      for (int r = 0; r < 4; r++)
#pragma unroll
        for (int c = 0; c < 4; c++)
          acc[r][c] += a[r].x * b[c].x + a[r].y * b[c].y + a[r].z * b[c].z + a[r].w * b[c].w;
    }
    __syncthreads();
  }
#pragma unroll
  for (int r = 0; r < 4; r++)
#pragma unroll
    for (int c = 0; c < 4; c++) {
      size_t idx = (size_t)(m0 + ty * 4 + r) * C_ + n0 + tx + 16 * c;
      z[idx] = x[idx] + acc[r][c];
    }
}

// ---------------------------------------------------------------------------
extern "C" void kernel_launch(void* const* d_in, const int* in_sizes, int n_in,
                              void* d_out, int out_size) {
  (void)in_sizes; (void)n_in; (void)out_size;
  const float* x = (const float*)d_in[0];
  const float* Wt = (const float*)d_in[1];
  const float* Wp = (const float*)d_in[2];
  const float* Wg = (const float*)d_in[3];
  const float* Wf = (const float*)d_in[4];
  float* z = (float*)d_out;

  proj_kernel<<<dim3(D_ / 64, (B_ * N_) / 64, 3), 256>>>(x, Wt, Wp, Wg);

  size_t smem = (size_t)(3 * 64 * 132 + 64 * 68) * sizeof(float);  // 118784 B
  cudaFuncSetAttribute(attn_kernel, cudaFuncAttributeMaxDynamicSharedMemorySize,
                       (int)smem);
  attn_kernel<<<dim3(N_ / 64, B_), 256, smem>>>();

  zout_kernel<<<dim3(C_ / 64, (B_ * N_) / 64), 256>>>(x, Wf, z);
}

// round 10
// speedup vs baseline: 1.1132x; 1.1132x over previous
#include <cuda_runtime.h>
#include <math.h>

#define B_ 4
#define N_ 4096
#define M_ 4095
#define C_ 256
#define D_ 128

// Scratch (device globals; no allocation allowed)
__device__ float g_theta[B_ * N_ * D_];
__device__ float g_phi[B_ * N_ * D_];
__device__ float g_gv[B_ * N_ * D_];
__device__ float g_y[B_ * N_ * D_];

// ---------------------------------------------------------------------------
// Kernel 1: projections  out[m][n] = sum_k x[m][k] * W[k][n]
// ---------------------------------------------------------------------------
__global__ __launch_bounds__(256) void proj_kernel(
    const float* __restrict__ x, const float* __restrict__ Wt,
    const float* __restrict__ Wp, const float* __restrict__ Wg) {
  __shared__ float As[64 * 36];
  __shared__ float Bs[64 * 36];

  const float* W;
  float* out;
  if (blockIdx.z == 0)      { W = Wt; out = g_theta; }
  else if (blockIdx.z == 1) { W = Wp; out = g_phi; }
  else                      { W = Wg; out = g_gv; }

  const int m0 = blockIdx.y * 64;
  const int n0 = blockIdx.x * 64;
  const int tid = threadIdx.x;
  const int tx = tid & 15, ty = tid >> 4;

  float acc[4][4];
#pragma unroll
  for (int r = 0; r < 4; r++)
#pragma unroll
    for (int c = 0; c < 4; c++) acc[r][c] = 0.0f;

  for (int k0 = 0; k0 < C_; k0 += 32) {
    {
      int row = tid >> 3;
      int c4 = tid & 7;
      float4 v0 = *(const float4*)(x + (size_t)(m0 + row) * C_ + k0 + c4 * 4);
      *(float4*)(As + row * 36 + c4 * 4) = v0;
      float4 v1 = *(const float4*)(x + (size_t)(m0 + row + 32) * C_ + k0 + c4 * 4);
      *(float4*)(As + (row + 32) * 36 + c4 * 4) = v1;
    }
    {
      int kr = tid >> 4;
      int c4 = tid & 15;
      float4 v0 = *(const float4*)(W + (size_t)(k0 + kr) * D_ + n0 + c4 * 4);
      Bs[(c4 * 4 + 0) * 36 + kr] = v0.x;
      Bs[(c4 * 4 + 1) * 36 + kr] = v0.y;
      Bs[(c4 * 4 + 2) * 36 + kr] = v0.z;
      Bs[(c4 * 4 + 3) * 36 + kr] = v0.w;
      float4 v1 = *(const float4*)(W + (size_t)(k0 + kr + 16) * D_ + n0 + c4 * 4);
      Bs[(c4 * 4 + 0) * 36 + kr + 16] = v1.x;
      Bs[(c4 * 4 + 1) * 36 + kr + 16] = v1.y;
      Bs[(c4 * 4 + 2) * 36 + kr + 16] = v1.z;
      Bs[(c4 * 4 + 3) * 36 + kr + 16] = v1.w;
    }
    __syncthreads();
#pragma unroll
    for (int kk = 0; kk < 32; kk += 4) {
      float4 a[4], b[4];
#pragma unroll
      for (int r = 0; r < 4; r++) a[r] = *(float4*)(As + (ty * 4 + r) * 36 + kk);
#pragma unroll
      for (int c = 0; c < 4; c++) b[c] = *(float4*)(Bs + (tx + 16 * c) * 36 + kk);
#pragma unroll
      for (int r = 0; r < 4; r++)
#pragma unroll
        for (int c = 0; c < 4; c++)
          acc[r][c] += a[r].x * b[c].x + a[r].y * b[c].y + a[r].z * b[c].z + a[r].w * b[c].w;
    }
    __syncthreads();
  }
#pragma unroll
  for (int r = 0; r < 4; r++)
#pragma unroll
    for (int c = 0; c < 4; c++)
      out[(size_t)(m0 + ty * 4 + r) * D_ + n0 + tx + 16 * c] = acc[r][c];
}

// ---------------------------------------------------------------------------
// TF32 helpers
// ---------------------------------------------------------------------------
__device__ __forceinline__ float to_tf32(float x) {
  asm("cvt.rna.tf32.f32 %0, %0;" : "+f"(x));
  return x;
}
__device__ __forceinline__ void mma_tf32(float d[4], const unsigned a[4],
                                         const unsigned b[2]) {
  asm volatile(
      "mma.sync.aligned.m16n8k8.row.col.f32.tf32.tf32.f32 "
      "{%0,%1,%2,%3},{%4,%5,%6,%7},{%8,%9},{%0,%1,%2,%3};\n"
      : "+f"(d[0]), "+f"(d[1]), "+f"(d[2]), "+f"(d[3])
      : "r"(a[0]), "r"(a[1]), "r"(a[2]), "r"(a[3]), "r"(b[0]), "r"(b[1]));
}

// ---------------------------------------------------------------------------
// Kernel 2: fused pooled flash attention, TF32 tensor cores with split-TF32
// (3xTF32) on the Q.K^T phase for fp32-grade scores; single TF32 on P.V.
// Block = 128 threads (4 warps), 64 queries; streams 64 K-tiles of 64 keys.
// Maxpool(2,1) fused into K/V smem load.
// ---------------------------------------------------------------------------
#define QS_STR 132
#define KS_STR 132
#define VS_STR 136  // bank-conflict-free B-fragment reads (8t+g)
#define PS_STR 68

__global__ __launch_bounds__(128) void attn_kernel() {
  extern __shared__ float smf[];
  float* Qb = smf;                    // [64][132] big
  float* Qs = Qb + 64 * QS_STR;       // [64][132] small residual
  float* Kb = Qs + 64 * QS_STR;       // [64][132] big (pooled phi)
  float* Ks = Kb + 64 * KS_STR;       // [64][132] small residual
  float* Vs = Ks + 64 * KS_STR;       // [64][136] pooled g (tf32)
  float* Ps = Vs + 64 * VS_STR;       // [64][68]
  const unsigned* Qbu = (const unsigned*)Qb;
  const unsigned* Qsu = (const unsigned*)Qs;
  const unsigned* Kbu = (const unsigned*)Kb;
  const unsigned* Ksu = (const unsigned*)Ks;
  const unsigned* Vu = (const unsigned*)Vs;
  const unsigned* Pu = (const unsigned*)Ps;

  const int b = blockIdx.y;
  const int q0 = blockIdx.x * 64;
  const float* th = g_theta + (size_t)b * N_ * D_;
  const float* ph = g_phi + (size_t)b * N_ * D_;
  const float* gv = g_gv + (size_t)b * N_ * D_;
  const int tid = threadIdx.x;
  const int w = tid >> 5;
  const int lane = tid & 31;
  const int g = lane >> 2;  // groupID (row within fragment)
  const int t = lane & 3;   // threadID_in_group

  // Load Q tile once; split into big (tf32) + small (tf32 of residual)
  for (int i = tid; i < 64 * 32; i += 128) {
    int row = i >> 5, c4 = i & 31;
    float4 v = *(const float4*)(th + (size_t)(q0 + row) * D_ + c4 * 4);
    float4 vb, vr;
    vb.x = to_tf32(v.x); vr.x = to_tf32(v.x - vb.x);
    vb.y = to_tf32(v.y); vr.y = to_tf32(v.y - vb.y);
    vb.z = to_tf32(v.z); vr.z = to_tf32(v.z - vb.z);
    vb.w = to_tf32(v.w); vr.w = to_tf32(v.w - vb.w);
    *(float4*)(Qb + row * QS_STR + c4 * 4) = vb;
    *(float4*)(Qs + row * QS_STR + c4 * 4) = vr;
  }

  float m0v = -INFINITY, m1v = -INFINITY;
  float l0v = 0.0f, l1v = 0.0f;
  float Oa[16][4];
#pragma unroll
  for (int dt = 0; dt < 16; dt++)
#pragma unroll
    for (int c = 0; c < 4; c++) Oa[dt][c] = 0.0f;

  for (int kt = 0; kt < 64; kt++) {
    const int k0 = kt * 64;
    const int nk = min(64, M_ - k0);

    __syncthreads();  // all warps done reading Kb/Ks/Vs from prev iter
    // Load + pool + tf32-split K, tf32 V
    for (int i = tid; i < 64 * 32; i += 128) {
      int row = i >> 5, c4 = i & 31;
      if (row < nk) {
        const float* p0 = ph + (size_t)(k0 + row) * D_ + c4 * 4;
        float4 a = *(const float4*)p0;
        float4 b2 = *(const float4*)(p0 + D_);
        float4 m4 = make_float4(fmaxf(a.x, b2.x), fmaxf(a.y, b2.y),
                                fmaxf(a.z, b2.z), fmaxf(a.w, b2.w));
        float4 vb, vr;
        vb.x = to_tf32(m4.x); vr.x = to_tf32(m4.x - vb.x);
        vb.y = to_tf32(m4.y); vr.y = to_tf32(m4.y - vb.y);
        vb.z = to_tf32(m4.z); vr.z = to_tf32(m4.z - vb.z);
        vb.w = to_tf32(m4.w); vr.w = to_tf32(m4.w - vb.w);
        *(float4*)(Kb + row * KS_STR + c4 * 4) = vb;
        *(float4*)(Ks + row * KS_STR + c4 * 4) = vr;
        const float* g0 = gv + (size_t)(k0 + row) * D_ + c4 * 4;
        a = *(const float4*)g0;
        b2 = *(const float4*)(g0 + D_);
        float4 r4;
        r4.x = to_tf32(fmaxf(a.x, b2.x)); r4.y = to_tf32(fmaxf(a.y, b2.y));
        r4.z = to_tf32(fmaxf(a.z, b2.z)); r4.w = to_tf32(fmaxf(a.w, b2.w));
        *(float4*)(Vs + row * VS_STR + c4 * 4) = r4;
      } else {
        float4 z4 = make_float4(0.f, 0.f, 0.f, 0.f);
        *(float4*)(Kb + row * KS_STR + c4 * 4) = z4;
        *(float4*)(Ks + row * KS_STR + c4 * 4) = z4;
        *(float4*)(Vs + row * VS_STR + c4 * 4) = z4;
      }
    }
    __syncthreads();

    // --- S = Q . K^T  (16 rows per warp x 64 keys), split-TF32 (3 mma) ---
    float sacc[8][4];
#pragma unroll
    for (int nt = 0; nt < 8; nt++)
#pragma unroll
      for (int c = 0; c < 4; c++) sacc[nt][c] = 0.0f;

    const int qrow = 16 * w + g;
#pragma unroll
    for (int kd = 0; kd < 16; kd++) {
      unsigned afb[4], afs[4];
      afb[0] = Qbu[qrow * QS_STR + kd * 8 + t];
      afb[1] = Qbu[(qrow + 8) * QS_STR + kd * 8 + t];
      afb[2] = Qbu[qrow * QS_STR + kd * 8 + t + 4];
      afb[3] = Qbu[(qrow + 8) * QS_STR + kd * 8 + t + 4];
      afs[0] = Qsu[qrow * QS_STR + kd * 8 + t];
      afs[1] = Qsu[(qrow + 8) * QS_STR + kd * 8 + t];
      afs[2] = Qsu[qrow * QS_STR + kd * 8 + t + 4];
      afs[3] = Qsu[(qrow + 8) * QS_STR + kd * 8 + t + 4];
#pragma unroll
      for (int nt = 0; nt < 8; nt++) {
        unsigned bfb[2], bfs[2];
        bfb[0] = Kbu[(nt * 8 + g) * KS_STR + kd * 8 + t];
        bfb[1] = Kbu[(nt * 8 + g) * KS_STR + kd * 8 + t + 4];
        bfs[0] = Ksu[(nt * 8 + g) * KS_STR + kd * 8 + t];
        bfs[1] = Ksu[(nt * 8 + g) * KS_STR + kd * 8 + t + 4];
        mma_tf32(sacc[nt], afb, bfb);
        mma_tf32(sacc[nt], afs, bfb);
        mma_tf32(sacc[nt], afb, bfs);
      }
    }

    // Mask invalid keys (only the final tile, key index >= M_)
    if (nk < 64) {
#pragma unroll
      for (int nt = 0; nt < 8; nt++) {
        int j0 = nt * 8 + 2 * t;
        if (k0 + j0 >= M_) { sacc[nt][0] = -INFINITY; sacc[nt][2] = -INFINITY; }
        if (k0 + j0 + 1 >= M_) { sacc[nt][1] = -INFINITY; sacc[nt][3] = -INFINITY; }
      }
    }

    // --- Online softmax (rows qrow and qrow+8) ---
    float mx0 = -INFINITY, mx1 = -INFINITY;
#pragma unroll
    for (int nt = 0; nt < 8; nt++) {
      mx0 = fmaxf(mx0, fmaxf(sacc[nt][0], sacc[nt][1]));
      mx1 = fmaxf(mx1, fmaxf(sacc[nt][2], sacc[nt][3]));
    }
#pragma unroll
    for (int off = 1; off < 4; off <<= 1) {
      mx0 = fmaxf(mx0, __shfl_xor_sync(0xffffffffu, mx0, off));
      mx1 = fmaxf(mx1, __shfl_xor_sync(0xffffffffu, mx1, off));
    }
    float mn0 = fmaxf(m0v, mx0), mn1 = fmaxf(m1v, mx1);
    float sc0 = __expf(m0v - mn0), sc1 = __expf(m1v - mn1);
    m0v = mn0; m1v = mn1;

    float s0 = 0.0f, s1 = 0.0f;
#pragma unroll
    for (int nt = 0; nt < 8; nt++) {
      float e0 = __expf(sacc[nt][0] - mn0);
      float e1 = __expf(sacc[nt][1] - mn0);
      float e2 = __expf(sacc[nt][2] - mn1);
      float e3 = __expf(sacc[nt][3] - mn1);
      s0 += e0 + e1;
      s1 += e2 + e3;
      int col = nt * 8 + 2 * t;
      Ps[qrow * PS_STR + col] = to_tf32(e0);
      Ps[qrow * PS_STR + col + 1] = to_tf32(e1);
      Ps[(qrow + 8) * PS_STR + col] = to_tf32(e2);
      Ps[(qrow + 8) * PS_STR + col + 1] = to_tf32(e3);
    }
#pragma unroll
    for (int off = 1; off < 4; off <<= 1) {
      s0 += __shfl_xor_sync(0xffffffffu, s0, off);
      s1 += __shfl_xor_sync(0xffffffffu, s1, off);
    }
    l0v = l0v * sc0 + s0;
    l1v = l1v * sc1 + s1;
#pragma unroll
    for (int dt = 0; dt < 16; dt++) {
      Oa[dt][0] *= sc0; Oa[dt][1] *= sc0;
      Oa[dt][2] *= sc1; Oa[dt][3] *= sc1;
    }
    __syncwarp();  // Ps strip is warp-private: warp-level visibility suffices

    // --- O += P . V  (16 rows x 128 dims), single tf32 mma ---
#pragma unroll
    for (int kk = 0; kk < 8; kk++) {
      unsigned af[4];
      af[0] = Pu[qrow * PS_STR + kk * 8 + t];
      af[1] = Pu[(qrow + 8) * PS_STR + kk * 8 + t];
      af[2] = Pu[qrow * PS_STR + kk * 8 + t + 4];
      af[3] = Pu[(qrow + 8) * PS_STR + kk * 8 + t + 4];
#pragma unroll
      for (int dt = 0; dt < 16; dt++) {
        unsigned bf[2];
        bf[0] = Vu[(kk * 8 + t) * VS_STR + dt * 8 + g];
        bf[1] = Vu[(kk * 8 + t + 4) * VS_STR + dt * 8 + g];
        mma_tf32(Oa[dt], af, bf);
      }
    }
  }

  // Normalize and store y
  float* yb = g_y + (size_t)b * N_ * D_;
  const float inv0 = 1.0f / l0v, inv1 = 1.0f / l1v;
  const int r0 = q0 + 16 * w + g, r1 = r0 + 8;
#pragma unroll
  for (int dt = 0; dt < 16; dt++) {
    int col = dt * 8 + 2 * t;
    *(float2*)(yb + (size_t)r0 * D_ + col) =
        make_float2(Oa[dt][0] * inv0, Oa[dt][1] * inv0);
    *(float2*)(yb + (size_t)r1 * D_ + col) =
        make_float2(Oa[dt][2] * inv1, Oa[dt][3] * inv1);
  }
}

// ---------------------------------------------------------------------------
// Kernel 3: z = x + y @ Wf.  M=16384, K=128, Nout=256.
// ---------------------------------------------------------------------------
__global__ __launch_bounds__(256) void zout_kernel(const float* __restrict__ x,
                                                   const float* __restrict__ Wf,
                                                   float* __restrict__ z) {
  __shared__ float As[64 * 36];
  __shared__ float Bs[64 * 36];

  const int m0 = blockIdx.y * 64;
  const int n0 = blockIdx.x * 64;
  const int tid = threadIdx.x;
  const int tx = tid & 15, ty = tid >> 4;

  float acc[4][4];
#pragma unroll
  for (int r = 0; r < 4; r++)
#pragma unroll
    for (int c = 0; c < 4; c++) acc[r][c] = 0.0f;

  for (int k0 = 0; k0 < D_; k0 += 32) {
    {
      int row = tid >> 3;
      int c4 = tid & 7;
      float4 v0 = *(const float4*)(g_y + (size_t)(m0 + row) * D_ + k0 + c4 * 4);
      *(float4*)(As + row * 36 + c4 * 4) = v0;
      float4 v1 = *(const float4*)(g_y + (size_t)(m0 + row + 32) * D_ + k0 + c4 * 4);
      *(float4*)(As + (row + 32) * 36 + c4 * 4) = v1;
    }
    {
      int kr = tid >> 4;
      int c4 = tid & 15;
      float4 v0 = *(const float4*)(Wf + (size_t)(k0 + kr) * C_ + n0 + c4 * 4);
      Bs[(c4 * 4 + 0) * 36 + kr] = v0.x;
      Bs[(c4 * 4 + 1) * 36 + kr] = v0.y;
      Bs[(c4 * 4 + 2) * 36 + kr] = v0.z;
      Bs[(c4 * 4 + 3) * 36 + kr] = v0.w;
      float4 v1 = *(const float4*)(Wf + (size_t)(k0 + kr + 16) * C_ + n0 + c4 * 4);
      Bs[(c4 * 4 + 0) * 36 + kr + 16] = v1.x;
      Bs[(c4 * 4 + 1) * 36 + kr + 16] = v1.y;
      Bs[(c4 * 4 + 2) * 36 + kr + 16] = v1.z;
      Bs[(c4 * 4 + 3) * 36 + kr + 16] = v1.w;
    }
    __syncthreads();
#pragma unroll
    for (int kk = 0; kk < 32; kk += 4) {
      float4 a[4], b[4];
#pragma unroll
      for (int r = 0; r < 4; r++) a[r] = *(float4*)(As + (ty * 4 + r) * 36 + kk);
#pragma unroll
      for (int c = 0; c < 4; c++) b[c] = *(float4*)(Bs + (tx + 16 * c) * 36 + kk);
#pragma unroll
      for (int r = 0; r < 4; r++)
#pragma unroll
        for (int c = 0; c < 4; c++)
          acc[r][c] += a[r].x * b[c].x + a[r].y * b[c].y + a[r].z * b[c].z + a[r].w * b[c].w;
    }
    __syncthreads();
  }
#pragma unroll
  for (int r = 0; r < 4; r++)
#pragma unroll
    for (int c = 0; c < 4; c++) {
      size_t idx = (size_t)(m0 + ty * 4 + r) * C_ + n0 + tx + 16 * c;
      z[idx] = x[idx] + acc[r][c];
    }
}

// ---------------------------------------------------------------------------
extern "C" void kernel_launch(void* const* d_in, const int* in_sizes, int n_in,
                              void* d_out, int out_size) {
  (void)in_sizes; (void)n_in; (void)out_size;
  const float* x = (const float*)d_in[0];
  const float* Wt = (const float*)d_in[1];
  const float* Wp = (const float*)d_in[2];
  const float* Wg = (const float*)d_in[3];
  const float* Wf = (const float*)d_in[4];
  float* z = (float*)d_out;

  proj_kernel<<<dim3(D_ / 64, (B_ * N_) / 64, 3), 256>>>(x, Wt, Wp, Wg);

  size_t smem = (size_t)(64 * (4 * QS_STR + VS_STR + PS_STR)) * sizeof(float);
  cudaFuncSetAttribute(attn_kernel, cudaFuncAttributeMaxDynamicSharedMemorySize,
                       (int)smem);
  attn_kernel<<<dim3(N_ / 64, B_), 128, smem>>>();

  zout_kernel<<<dim3(C_ / 64, (B_ * N_) / 64), 256>>>(x, Wf, z);
}

// round 11
// speedup vs baseline: 1.5934x; 1.4313x over previous
#include <cuda_runtime.h>
#include <math.h>

#define B_ 4
#define N_ 4096
#define M_ 4095
#define C_ 256
#define D_ 128

// Scratch (device globals; no allocation allowed)
__device__ float g_theta[B_ * N_ * D_];
__device__ float g_phi[B_ * N_ * D_];
__device__ float g_gv[B_ * N_ * D_];
__device__ float g_y[B_ * N_ * D_];

// ---------------------------------------------------------------------------
// Kernel 1: projections  out[m][n] = sum_k x[m][k] * W[k][n]
// ---------------------------------------------------------------------------
__global__ __launch_bounds__(256) void proj_kernel(
    const float* __restrict__ x, const float* __restrict__ Wt,
    const float* __restrict__ Wp, const float* __restrict__ Wg) {
  __shared__ float As[64 * 36];
  __shared__ float Bs[64 * 36];

  const float* W;
  float* out;
  if (blockIdx.z == 0)      { W = Wt; out = g_theta; }
  else if (blockIdx.z == 1) { W = Wp; out = g_phi; }
  else                      { W = Wg; out = g_gv; }

  const int m0 = blockIdx.y * 64;
  const int n0 = blockIdx.x * 64;
  const int tid = threadIdx.x;
  const int tx = tid & 15, ty = tid >> 4;

  float acc[4][4];
#pragma unroll
  for (int r = 0; r < 4; r++)
#pragma unroll
    for (int c = 0; c < 4; c++) acc[r][c] = 0.0f;

  for (int k0 = 0; k0 < C_; k0 += 32) {
    {
      int row = tid >> 3;
      int c4 = tid & 7;
      float4 v0 = *(const float4*)(x + (size_t)(m0 + row) * C_ + k0 + c4 * 4);
      *(float4*)(As + row * 36 + c4 * 4) = v0;
      float4 v1 = *(const float4*)(x + (size_t)(m0 + row + 32) * C_ + k0 + c4 * 4);
      *(float4*)(As + (row + 32) * 36 + c4 * 4) = v1;
    }
    {
      int kr = tid >> 4;
      int c4 = tid & 15;
      float4 v0 = *(const float4*)(W + (size_t)(k0 + kr) * D_ + n0 + c4 * 4);
      Bs[(c4 * 4 + 0) * 36 + kr] = v0.x;
      Bs[(c4 * 4 + 1) * 36 + kr] = v0.y;
      Bs[(c4 * 4 + 2) * 36 + kr] = v0.z;
      Bs[(c4 * 4 + 3) * 36 + kr] = v0.w;
      float4 v1 = *(const float4*)(W + (size_t)(k0 + kr + 16) * D_ + n0 + c4 * 4);
      Bs[(c4 * 4 + 0) * 36 + kr + 16] = v1.x;
      Bs[(c4 * 4 + 1) * 36 + kr + 16] = v1.y;
      Bs[(c4 * 4 + 2) * 36 + kr + 16] = v1.z;
      Bs[(c4 * 4 + 3) * 36 + kr + 16] = v1.w;
    }
    __syncthreads();
#pragma unroll
    for (int kk = 0; kk < 32; kk += 4) {
      float4 a[4], b[4];
#pragma unroll
      for (int r = 0; r < 4; r++) a[r] = *(float4*)(As + (ty * 4 + r) * 36 + kk);
#pragma unroll
      for (int c = 0; c < 4; c++) b[c] = *(float4*)(Bs + (tx + 16 * c) * 36 + kk);
#pragma unroll
      for (int r = 0; r < 4; r++)
#pragma unroll
        for (int c = 0; c < 4; c++)
          acc[r][c] += a[r].x * b[c].x + a[r].y * b[c].y + a[r].z * b[c].z + a[r].w * b[c].w;
    }
    __syncthreads();
  }
#pragma unroll
  for (int r = 0; r < 4; r++)
#pragma unroll
    for (int c = 0; c < 4; c++)
      out[(size_t)(m0 + ty * 4 + r) * D_ + n0 + tx + 16 * c] = acc[r][c];
}

// ---------------------------------------------------------------------------
// TF32 helpers
// ---------------------------------------------------------------------------
__device__ __forceinline__ float to_tf32(float x) {
  asm("cvt.rna.tf32.f32 %0, %0;" : "+f"(x));
  return x;
}
__device__ __forceinline__ void mma_tf32(float d[4], const unsigned a[4],
                                         const unsigned b[2]) {
  asm volatile(
      "mma.sync.aligned.m16n8k8.row.col.f32.tf32.tf32.f32 "
      "{%0,%1,%2,%3},{%4,%5,%6,%7},{%8,%9},{%0,%1,%2,%3};\n"
      : "+f"(d[0]), "+f"(d[1]), "+f"(d[2]), "+f"(d[3])
      : "r"(a[0]), "r"(a[1]), "r"(a[2]), "r"(a[3]), "r"(b[0]), "r"(b[1]));
}

// ---------------------------------------------------------------------------
// Kernel 2: fused pooled flash attention, split-TF32 QK^T + TF32 PV,
// 8 warps: warp w owns query rows 16*(w&3), key half (w>>2) of each 64-key
// tile. Shared K/V smem; only the row-max crosses warps per tile; l and O
// kept as per-half partials, merged once at the end.
// ---------------------------------------------------------------------------
#define QS_STR 132
#define KS_STR 132
#define VS_STR 136
#define PS_STR 68
#define OR_STR 136

__global__ __launch_bounds__(256) void attn_kernel() {
  extern __shared__ float smf[];
  float* Qb = smf;                    // [64][132] big
  float* Qs = Qb + 64 * QS_STR;       // [64][132] small residual
  float* Kb = Qs + 64 * QS_STR;       // [64][132] big (pooled phi)
  float* Ks = Kb + 64 * KS_STR;       // [64][132] small residual
  float* Vs = Ks + 64 * KS_STR;       // [64][136] pooled g (tf32)
  float* Ps = Vs + 64 * VS_STR;       // [64][68]
  float* redm = Ps + 64 * PS_STR;     // [2][64] per-half row max
  float* lred = redm + 128;           // [64] half-1 l partials (separate: no race)
  float* Ored = Kb;                   // [64][136] end-of-loop O merge (reuses Kb/Ks)
  const unsigned* Qbu = (const unsigned*)Qb;
  const unsigned* Qsu = (const unsigned*)Qs;
  const unsigned* Kbu = (const unsigned*)Kb;
  const unsigned* Ksu = (const unsigned*)Ks;
  const unsigned* Vu = (const unsigned*)Vs;
  const unsigned* Pu = (const unsigned*)Ps;

  const int b = blockIdx.y;
  const int q0 = blockIdx.x * 64;
  const float* th = g_theta + (size_t)b * N_ * D_;
  const float* ph = g_phi + (size_t)b * N_ * D_;
  const float* gv = g_gv + (size_t)b * N_ * D_;
  const int tid = threadIdx.x;
  const int w = tid >> 5;
  const int wg = w & 3;     // query group (rows 16*wg .. 16*wg+15)
  const int half = w >> 2;  // key half (0: keys 0-31, 1: keys 32-63)
  const int jb = half * 32; // key column base within tile
  const int lane = tid & 31;
  const int g = lane >> 2;
  const int t = lane & 3;
  const int r0i = 16 * wg + g;  // fragment row (and r0i+8)

  // Load Q tile once; split into big (tf32) + small (tf32 of residual)
  for (int i = tid; i < 64 * 32; i += 256) {
    int row = i >> 5, c4 = i & 31;
    float4 v = *(const float4*)(th + (size_t)(q0 + row) * D_ + c4 * 4);
    float4 vb, vr;
    vb.x = to_tf32(v.x); vr.x = to_tf32(v.x - vb.x);
    vb.y = to_tf32(v.y); vr.y = to_tf32(v.y - vb.y);
    vb.z = to_tf32(v.z); vr.z = to_tf32(v.z - vb.z);
    vb.w = to_tf32(v.w); vr.w = to_tf32(v.w - vb.w);
    *(float4*)(Qb + row * QS_STR + c4 * 4) = vb;
    *(float4*)(Qs + row * QS_STR + c4 * 4) = vr;
  }

  float m0v = -INFINITY, m1v = -INFINITY;
  float l0v = 0.0f, l1v = 0.0f;  // per-half partial row sums
  float Oa[16][4];               // per-half partial O
#pragma unroll
  for (int dt = 0; dt < 16; dt++)
#pragma unroll
    for (int c = 0; c < 4; c++) Oa[dt][c] = 0.0f;

  for (int kt = 0; kt < 64; kt++) {
    const int k0 = kt * 64;
    const int nk = min(64, M_ - k0);

    __syncthreads();  // all warps done reading Kb/Ks/Vs (+redm) from prev iter
    // Load + pool + tf32-split K, tf32 V
    for (int i = tid; i < 64 * 32; i += 256) {
      int row = i >> 5, c4 = i & 31;
      if (row < nk) {
        const float* p0 = ph + (size_t)(k0 + row) * D_ + c4 * 4;
        float4 a = *(const float4*)p0;
        float4 b2 = *(const float4*)(p0 + D_);
        float4 m4 = make_float4(fmaxf(a.x, b2.x), fmaxf(a.y, b2.y),
                                fmaxf(a.z, b2.z), fmaxf(a.w, b2.w));
        float4 vb, vr;
        vb.x = to_tf32(m4.x); vr.x = to_tf32(m4.x - vb.x);
        vb.y = to_tf32(m4.y); vr.y = to_tf32(m4.y - vb.y);
        vb.z = to_tf32(m4.z); vr.z = to_tf32(m4.z - vb.z);
        vb.w = to_tf32(m4.w); vr.w = to_tf32(m4.w - vb.w);
        *(float4*)(Kb + row * KS_STR + c4 * 4) = vb;
        *(float4*)(Ks + row * KS_STR + c4 * 4) = vr;
        const float* g0 = gv + (size_t)(k0 + row) * D_ + c4 * 4;
        a = *(const float4*)g0;
        b2 = *(const float4*)(g0 + D_);
        float4 r4;
        r4.x = to_tf32(fmaxf(a.x, b2.x)); r4.y = to_tf32(fmaxf(a.y, b2.y));
        r4.z = to_tf32(fmaxf(a.z, b2.z)); r4.w = to_tf32(fmaxf(a.w, b2.w));
        *(float4*)(Vs + row * VS_STR + c4 * 4) = r4;
      } else {
        float4 z4 = make_float4(0.f, 0.f, 0.f, 0.f);
        *(float4*)(Kb + row * KS_STR + c4 * 4) = z4;
        *(float4*)(Ks + row * KS_STR + c4 * 4) = z4;
        *(float4*)(Vs + row * VS_STR + c4 * 4) = z4;
      }
    }
    __syncthreads();

    // --- S = Q . K^T  (16 rows x 32 keys per warp), split-TF32 (3 mma) ---
    float sacc[4][4];
#pragma unroll
    for (int nt = 0; nt < 4; nt++)
#pragma unroll
      for (int c = 0; c < 4; c++) sacc[nt][c] = 0.0f;

#pragma unroll
    for (int kd = 0; kd < 16; kd++) {
      unsigned afb[4], afs[4];
      afb[0] = Qbu[r0i * QS_STR + kd * 8 + t];
      afb[1] = Qbu[(r0i + 8) * QS_STR + kd * 8 + t];
      afb[2] = Qbu[r0i * QS_STR + kd * 8 + t + 4];
      afb[3] = Qbu[(r0i + 8) * QS_STR + kd * 8 + t + 4];
      afs[0] = Qsu[r0i * QS_STR + kd * 8 + t];
      afs[1] = Qsu[(r0i + 8) * QS_STR + kd * 8 + t];
      afs[2] = Qsu[r0i * QS_STR + kd * 8 + t + 4];
      afs[3] = Qsu[(r0i + 8) * QS_STR + kd * 8 + t + 4];
#pragma unroll
      for (int nt = 0; nt < 4; nt++) {
        int krow = jb + nt * 8 + g;
        unsigned bfb[2], bfs[2];
        bfb[0] = Kbu[krow * KS_STR + kd * 8 + t];
        bfb[1] = Kbu[krow * KS_STR + kd * 8 + t + 4];
        bfs[0] = Ksu[krow * KS_STR + kd * 8 + t];
        bfs[1] = Ksu[krow * KS_STR + kd * 8 + t + 4];
        mma_tf32(sacc[nt], afb, bfb);
        mma_tf32(sacc[nt], afs, bfb);
        mma_tf32(sacc[nt], afb, bfs);
      }
    }

    // Mask invalid keys (final tile only)
    if (nk < 64) {
#pragma unroll
      for (int nt = 0; nt < 4; nt++) {
        int j0 = jb + nt * 8 + 2 * t;
        if (k0 + j0 >= M_) { sacc[nt][0] = -INFINITY; sacc[nt][2] = -INFINITY; }
        if (k0 + j0 + 1 >= M_) { sacc[nt][1] = -INFINITY; sacc[nt][3] = -INFINITY; }
      }
    }

    // --- Per-half row max, then cross-half combine via smem ---
    float mx0 = -INFINITY, mx1 = -INFINITY;
#pragma unroll
    for (int nt = 0; nt < 4; nt++) {
      mx0 = fmaxf(mx0, fmaxf(sacc[nt][0], sacc[nt][1]));
      mx1 = fmaxf(mx1, fmaxf(sacc[nt][2], sacc[nt][3]));
    }
#pragma unroll
    for (int off = 1; off < 4; off <<= 1) {
      mx0 = fmaxf(mx0, __shfl_xor_sync(0xffffffffu, mx0, off));
      mx1 = fmaxf(mx1, __shfl_xor_sync(0xffffffffu, mx1, off));
    }
    if (t == 0) {
      redm[half * 64 + r0i] = mx0;
      redm[half * 64 + r0i + 8] = mx1;
    }
    __syncthreads();
    mx0 = fmaxf(mx0, redm[(1 - half) * 64 + r0i]);
    mx1 = fmaxf(mx1, redm[(1 - half) * 64 + r0i + 8]);

    float mn0 = fmaxf(m0v, mx0), mn1 = fmaxf(m1v, mx1);
    float sc0 = __expf(m0v - mn0), sc1 = __expf(m1v - mn1);
    m0v = mn0; m1v = mn1;

    float s0 = 0.0f, s1 = 0.0f;
#pragma unroll
    for (int nt = 0; nt < 4; nt++) {
      float e0 = __expf(sacc[nt][0] - mn0);
      float e1 = __expf(sacc[nt][1] - mn0);
      float e2 = __expf(sacc[nt][2] - mn1);
      float e3 = __expf(sacc[nt][3] - mn1);
      s0 += e0 + e1;
      s1 += e2 + e3;
      int col = jb + nt * 8 + 2 * t;
      Ps[r0i * PS_STR + col] = to_tf32(e0);
      Ps[r0i * PS_STR + col + 1] = to_tf32(e1);
      Ps[(r0i + 8) * PS_STR + col] = to_tf32(e2);
      Ps[(r0i + 8) * PS_STR + col + 1] = to_tf32(e3);
    }
#pragma unroll
    for (int off = 1; off < 4; off <<= 1) {
      s0 += __shfl_xor_sync(0xffffffffu, s0, off);
      s1 += __shfl_xor_sync(0xffffffffu, s1, off);
    }
    l0v = l0v * sc0 + s0;  // per-half partial (sc identical across halves)
    l1v = l1v * sc1 + s1;
#pragma unroll
    for (int dt = 0; dt < 16; dt++) {
      Oa[dt][0] *= sc0; Oa[dt][1] *= sc0;
      Oa[dt][2] *= sc1; Oa[dt][3] *= sc1;
    }
    __syncwarp();  // own-half P strip is warp-private

    // --- O += P . V over own key half (4 kk of 8 keys) ---
#pragma unroll
    for (int kk = 0; kk < 4; kk++) {
      unsigned af[4];
      af[0] = Pu[r0i * PS_STR + jb + kk * 8 + t];
      af[1] = Pu[(r0i + 8) * PS_STR + jb + kk * 8 + t];
      af[2] = Pu[r0i * PS_STR + jb + kk * 8 + t + 4];
      af[3] = Pu[(r0i + 8) * PS_STR + jb + kk * 8 + t + 4];
#pragma unroll
      for (int dt = 0; dt < 16; dt++) {
        unsigned bf[2];
        bf[0] = Vu[(jb + kk * 8 + t) * VS_STR + dt * 8 + g];
        bf[1] = Vu[(jb + kk * 8 + t + 4) * VS_STR + dt * 8 + g];
        mma_tf32(Oa[dt], af, bf);
      }
    }
  }

  // --- Merge halves: half 1 exports O partials + l; half 0 sums and stores ---
  if (half == 1) {
    if (t == 0) {
      lred[r0i] = l0v;
      lred[r0i + 8] = l1v;
    }
#pragma unroll
    for (int dt = 0; dt < 16; dt++) {
      *(float2*)(Ored + r0i * OR_STR + dt * 8 + 2 * t) =
          make_float2(Oa[dt][0], Oa[dt][1]);
      *(float2*)(Ored + (r0i + 8) * OR_STR + dt * 8 + 2 * t) =
          make_float2(Oa[dt][2], Oa[dt][3]);
    }
  }
  __syncthreads();
  if (half == 0) {
    float lt0 = l0v + lred[r0i];
    float lt1 = l1v + lred[r0i + 8];
    float inv0 = 1.0f / lt0, inv1 = 1.0f / lt1;
    float* yb = g_y + (size_t)b * N_ * D_;
#pragma unroll
    for (int dt = 0; dt < 16; dt++) {
      int col = dt * 8 + 2 * t;
      float2 p0 = *(float2*)(Ored + r0i * OR_STR + col);
      float2 p1 = *(float2*)(Ored + (r0i + 8) * OR_STR + col);
      *(float2*)(yb + (size_t)(q0 + r0i) * D_ + col) =
          make_float2((Oa[dt][0] + p0.x) * inv0, (Oa[dt][1] + p0.y) * inv0);
      *(float2*)(yb + (size_t)(q0 + r0i + 8) * D_ + col) =
          make_float2((Oa[dt][2] + p1.x) * inv1, (Oa[dt][3] + p1.y) * inv1);
    }
  }
}

// ---------------------------------------------------------------------------
// Kernel 3: z = x + y @ Wf.  M=16384, K=128, Nout=256.
// ---------------------------------------------------------------------------
__global__ __launch_bounds__(256) void zout_kernel(const float* __restrict__ x,
                                                   const float* __restrict__ Wf,
                                                   float* __restrict__ z) {
  __shared__ float As[64 * 36];
  __shared__ float Bs[64 * 36];

  const int m0 = blockIdx.y * 64;
  const int n0 = blockIdx.x * 64;
  const int tid = threadIdx.x;
  const int tx = tid & 15, ty = tid >> 4;

  float acc[4][4];
#pragma unroll
  for (int r = 0; r < 4; r++)
#pragma unroll
    for (int c = 0; c < 4; c++) acc[r][c] = 0.0f;

  for (int k0 = 0; k0 < D_; k0 += 32) {
    {
      int row = tid >> 3;
      int c4 = tid & 7;
      float4 v0 = *(const float4*)(g_y + (size_t)(m0 + row) * D_ + k0 + c4 * 4);
      *(float4*)(As + row * 36 + c4 * 4) = v0;
      float4 v1 = *(const float4*)(g_y + (size_t)(m0 + row + 32) * D_ + k0 + c4 * 4);
      *(float4*)(As + (row + 32) * 36 + c4 * 4) = v1;
    }
    {
      int kr = tid >> 4;
      int c4 = tid & 15;
      float4 v0 = *(const float4*)(Wf + (size_t)(k0 + kr) * C_ + n0 + c4 * 4);
      Bs[(c4 * 4 + 0) * 36 + kr] = v0.x;
      Bs[(c4 * 4 + 1) * 36 + kr] = v0.y;
      Bs[(c4 * 4 + 2) * 36 + kr] = v0.z;
      Bs[(c4 * 4 + 3) * 36 + kr] = v0.w;
      float4 v1 = *(const float4*)(Wf + (size_t)(k0 + kr + 16) * C_ + n0 + c4 * 4);
      Bs[(c4 * 4 + 0) * 36 + kr + 16] = v1.x;
      Bs[(c4 * 4 + 1) * 36 + kr + 16] = v1.y;
      Bs[(c4 * 4 + 2) * 36 + kr + 16] = v1.z;
      Bs[(c4 * 4 + 3) * 36 + kr + 16] = v1.w;
    }
    __syncthreads();
#pragma unroll
    for (int kk = 0; kk < 32; kk += 4) {
      float4 a[4], b[4];
#pragma unroll
      for (int r = 0; r < 4; r++) a[r] = *(float4*)(As + (ty * 4 + r) * 36 + kk);
#pragma unroll
      for (int c = 0; c < 4; c++) b[c] = *(float4*)(Bs + (tx + 16 * c) * 36 + kk);
#pragma unroll
      for (int r = 0; r < 4; r++)
#pragma unroll
        for (int c = 0; c < 4; c++)
          acc[r][c] += a[r].x * b[c].x + a[r].y * b[c].y + a[r].z * b[c].z + a[r].w * b[c].w;
    }
    __syncthreads();
  }
#pragma unroll
  for (int r = 0; r < 4; r++)
#pragma unroll
    for (int c = 0; c < 4; c++) {
      size_t idx = (size_t)(m0 + ty * 4 + r) * C_ + n0 + tx + 16 * c;
      z[idx] = x[idx] + acc[r][c];
    }
}

// ---------------------------------------------------------------------------
extern "C" void kernel_launch(void* const* d_in, const int* in_sizes, int n_in,
                              void* d_out, int out_size) {
  (void)in_sizes; (void)n_in; (void)out_size;
  const float* x = (const float*)d_in[0];
  const float* Wt = (const float*)d_in[1];
  const float* Wp = (const float*)d_in[2];
  const float* Wg = (const float*)d_in[3];
  const float* Wf = (const float*)d_in[4];
  float* z = (float*)d_out;

  proj_kernel<<<dim3(D_ / 64, (B_ * N_) / 64, 3), 256>>>(x, Wt, Wp, Wg);

  size_t smem =
      (size_t)(64 * (4 * QS_STR + VS_STR + PS_STR) + 128 + 64) * sizeof(float);
  cudaFuncSetAttribute(attn_kernel, cudaFuncAttributeMaxDynamicSharedMemorySize,
                       (int)smem);
  attn_kernel<<<dim3(N_ / 64, B_), 256, smem>>>();

  zout_kernel<<<dim3(C_ / 64, (B_ * N_) / 64), 256>>>(x, Wf, z);
}

// round 13
// speedup vs baseline: 1.8249x; 1.1453x over previous
#include <cuda_runtime.h>
#include <math.h>

#define B_ 4
#define N_ 4096
#define M_ 4095
#define C_ 256
#define D_ 128

// Scratch (device globals; no allocation allowed)
__device__ float g_theta[B_ * N_ * D_];
__device__ float g_phi[B_ * N_ * D_];
__device__ float g_gv[B_ * N_ * D_];
__device__ float g_y[B_ * N_ * D_];

// ---------------------------------------------------------------------------
// Kernel 1: projections  out[m][n] = sum_k x[m][k] * W[k][n]
// ---------------------------------------------------------------------------
__global__ __launch_bounds__(256) void proj_kernel(
    const float* __restrict__ x, const float* __restrict__ Wt,
    const float* __restrict__ Wp, const float* __restrict__ Wg) {
  __shared__ float As[64 * 36];
  __shared__ float Bs[64 * 36];

  const float* W;
  float* out;
  if (blockIdx.z == 0)      { W = Wt; out = g_theta; }
  else if (blockIdx.z == 1) { W = Wp; out = g_phi; }
  else                      { W = Wg; out = g_gv; }

  const int m0 = blockIdx.y * 64;
  const int n0 = blockIdx.x * 64;
  const int tid = threadIdx.x;
  const int tx = tid & 15, ty = tid >> 4;

  float acc[4][4];
#pragma unroll
  for (int r = 0; r < 4; r++)
#pragma unroll
    for (int c = 0; c < 4; c++) acc[r][c] = 0.0f;

  for (int k0 = 0; k0 < C_; k0 += 32) {
    {
      int row = tid >> 3;
      int c4 = tid & 7;
      float4 v0 = *(const float4*)(x + (size_t)(m0 + row) * C_ + k0 + c4 * 4);
      *(float4*)(As + row * 36 + c4 * 4) = v0;
      float4 v1 = *(const float4*)(x + (size_t)(m0 + row + 32) * C_ + k0 + c4 * 4);
      *(float4*)(As + (row + 32) * 36 + c4 * 4) = v1;
    }
    {
      int kr = tid >> 4;
      int c4 = tid & 15;
      float4 v0 = *(const float4*)(W + (size_t)(k0 + kr) * D_ + n0 + c4 * 4);
      Bs[(c4 * 4 + 0) * 36 + kr] = v0.x;
      Bs[(c4 * 4 + 1) * 36 + kr] = v0.y;
      Bs[(c4 * 4 + 2) * 36 + kr] = v0.z;
      Bs[(c4 * 4 + 3) * 36 + kr] = v0.w;
      float4 v1 = *(const float4*)(W + (size_t)(k0 + kr + 16) * D_ + n0 + c4 * 4);
      Bs[(c4 * 4 + 0) * 36 + kr + 16] = v1.x;
      Bs[(c4 * 4 + 1) * 36 + kr + 16] = v1.y;
      Bs[(c4 * 4 + 2) * 36 + kr + 16] = v1.z;
      Bs[(c4 * 4 + 3) * 36 + kr + 16] = v1.w;
    }
    __syncthreads();
#pragma unroll
    for (int kk = 0; kk < 32; kk += 4) {
      float4 a[4], b[4];
#pragma unroll
      for (int r = 0; r < 4; r++) a[r] = *(float4*)(As + (ty * 4 + r) * 36 + kk);
#pragma unroll
      for (int c = 0; c < 4; c++) b[c] = *(float4*)(Bs + (tx + 16 * c) * 36 + kk);
#pragma unroll
      for (int r = 0; r < 4; r++)
#pragma unroll
        for (int c = 0; c < 4; c++)
          acc[r][c] += a[r].x * b[c].x + a[r].y * b[c].y + a[r].z * b[c].z + a[r].w * b[c].w;
    }
    __syncthreads();
  }
#pragma unroll
  for (int r = 0; r < 4; r++)
#pragma unroll
    for (int c = 0; c < 4; c++)
      out[(size_t)(m0 + ty * 4 + r) * D_ + n0 + tx + 16 * c] = acc[r][c];
}

// ---------------------------------------------------------------------------
// TF32 helpers
// ---------------------------------------------------------------------------
__device__ __forceinline__ float to_tf32(float x) {
  asm("cvt.rna.tf32.f32 %0, %0;" : "+f"(x));
  return x;
}
__device__ __forceinline__ void mma_tf32(float d[4], const unsigned a[4],
                                         const unsigned b[2]) {
  asm volatile(
      "mma.sync.aligned.m16n8k8.row.col.f32.tf32.tf32.f32 "
      "{%0,%1,%2,%3},{%4,%5,%6,%7},{%8,%9},{%0,%1,%2,%3};\n"
      : "+f"(d[0]), "+f"(d[1]), "+f"(d[2]), "+f"(d[3])
      : "r"(a[0]), "r"(a[1]), "r"(a[2]), "r"(a[3]), "r"(b[0]), "r"(b[1]));
}

// ---------------------------------------------------------------------------
// Kernel 2: fused pooled flash attention, split-TF32 QK^T + TF32 PV.
// 16 warps (4/SMSP): warp w owns query rows 16*(w&3), key QUARTER (w>>2)
// (16 keys) of each 64-key tile. Shared K/V smem; row-max crosses warps per
// tile via redm[4][64]; l and O kept per-quarter, merged once at the end.
// ---------------------------------------------------------------------------
#define QS_STR 132
#define KS_STR 132
#define VS_STR 136
#define PS_STR 68
#define OR_STR 132

__global__ __launch_bounds__(512) void attn_kernel() {
  extern __shared__ float smf[];
  float* Qb = smf;                    // [64][132] big
  float* Qs = Qb + 64 * QS_STR;       // [64][132] small residual
  float* Kb = Qs + 64 * QS_STR;       // [64][132] big (pooled phi)
  float* Ks = Kb + 64 * KS_STR;       // [64][132] small residual
  float* Vs = Ks + 64 * KS_STR;       // [64][136] pooled g (tf32)
  float* Ps = Vs + 64 * VS_STR;       // [64][68]
  float* redm = Ps + 64 * PS_STR;     // [4][64] per-quarter row max
  float* lred = redm + 256;           // [3][64] quarters 1-3 l partials
  // End-of-loop O merge reuses dead K/V planes (guarded by __syncthreads):
  // quarter 1 -> Kb, quarter 2 -> Ks, quarter 3 -> Vs, stride OR_STR=132.
  const unsigned* Qbu = (const unsigned*)Qb;
  const unsigned* Qsu = (const unsigned*)Qs;
  const unsigned* Kbu = (const unsigned*)Kb;
  const unsigned* Ksu = (const unsigned*)Ks;
  const unsigned* Vu = (const unsigned*)Vs;
  const unsigned* Pu = (const unsigned*)Ps;

  const int b = blockIdx.y;
  const int q0 = blockIdx.x * 64;
  const float* th = g_theta + (size_t)b * N_ * D_;
  const float* ph = g_phi + (size_t)b * N_ * D_;
  const float* gv = g_gv + (size_t)b * N_ * D_;
  const int tid = threadIdx.x;
  const int w = tid >> 5;
  const int wg = w & 3;       // query group (rows 16*wg .. 16*wg+15)
  const int quar = w >> 2;    // key quarter (16 keys)
  const int jb = quar * 16;   // key column base within tile
  const int lane = tid & 31;
  const int g = lane >> 2;
  const int t = lane & 3;
  const int r0i = 16 * wg + g;  // fragment row (and r0i+8)

  // Load Q tile once; split into big (tf32) + small (tf32 of residual)
  for (int i = tid; i < 64 * 32; i += 512) {
    int row = i >> 5, c4 = i & 31;
    float4 v = *(const float4*)(th + (size_t)(q0 + row) * D_ + c4 * 4);
    float4 vb, vr;
    vb.x = to_tf32(v.x); vr.x = to_tf32(v.x - vb.x);
    vb.y = to_tf32(v.y); vr.y = to_tf32(v.y - vb.y);
    vb.z = to_tf32(v.z); vr.z = to_tf32(v.z - vb.z);
    vb.w = to_tf32(v.w); vr.w = to_tf32(v.w - vb.w);
    *(float4*)(Qb + row * QS_STR + c4 * 4) = vb;
    *(float4*)(Qs + row * QS_STR + c4 * 4) = vr;
  }

  float m0v = -INFINITY, m1v = -INFINITY;
  float l0v = 0.0f, l1v = 0.0f;  // per-quarter partial row sums
  float Oa[16][4];               // per-quarter partial O
#pragma unroll
  for (int dt = 0; dt < 16; dt++)
#pragma unroll
    for (int c = 0; c < 4; c++) Oa[dt][c] = 0.0f;

  for (int kt = 0; kt < 64; kt++) {
    const int k0 = kt * 64;
    const int nk = min(64, M_ - k0);

    __syncthreads();  // all warps done reading Kb/Ks/Vs (+redm) from prev iter
    // Load + pool + tf32-split K, tf32 V
    for (int i = tid; i < 64 * 32; i += 512) {
      int row = i >> 5, c4 = i & 31;
      if (row < nk) {
        const float* p0 = ph + (size_t)(k0 + row) * D_ + c4 * 4;
        float4 a = *(const float4*)p0;
        float4 b2 = *(const float4*)(p0 + D_);
        float4 m4 = make_float4(fmaxf(a.x, b2.x), fmaxf(a.y, b2.y),
                                fmaxf(a.z, b2.z), fmaxf(a.w, b2.w));
        float4 vb, vr;
        vb.x = to_tf32(m4.x); vr.x = to_tf32(m4.x - vb.x);
        vb.y = to_tf32(m4.y); vr.y = to_tf32(m4.y - vb.y);
        vb.z = to_tf32(m4.z); vr.z = to_tf32(m4.z - vb.z);
        vb.w = to_tf32(m4.w); vr.w = to_tf32(m4.w - vb.w);
        *(float4*)(Kb + row * KS_STR + c4 * 4) = vb;
        *(float4*)(Ks + row * KS_STR + c4 * 4) = vr;
        const float* g0 = gv + (size_t)(k0 + row) * D_ + c4 * 4;
        a = *(const float4*)g0;
        b2 = *(const float4*)(g0 + D_);
        float4 r4;
        r4.x = to_tf32(fmaxf(a.x, b2.x)); r4.y = to_tf32(fmaxf(a.y, b2.y));
        r4.z = to_tf32(fmaxf(a.z, b2.z)); r4.w = to_tf32(fmaxf(a.w, b2.w));
        *(float4*)(Vs + row * VS_STR + c4 * 4) = r4;
      } else {
        float4 z4 = make_float4(0.f, 0.f, 0.f, 0.f);
        *(float4*)(Kb + row * KS_STR + c4 * 4) = z4;
        *(float4*)(Ks + row * KS_STR + c4 * 4) = z4;
        *(float4*)(Vs + row * VS_STR + c4 * 4) = z4;
      }
    }
    __syncthreads();

    // --- S = Q . K^T  (16 rows x 16 keys per warp), split-TF32 (3 mma) ---
    float sacc[2][4];
#pragma unroll
    for (int nt = 0; nt < 2; nt++)
#pragma unroll
      for (int c = 0; c < 4; c++) sacc[nt][c] = 0.0f;

#pragma unroll
    for (int kd = 0; kd < 16; kd++) {
      unsigned afb[4], afs[4];
      afb[0] = Qbu[r0i * QS_STR + kd * 8 + t];
      afb[1] = Qbu[(r0i + 8) * QS_STR + kd * 8 + t];
      afb[2] = Qbu[r0i * QS_STR + kd * 8 + t + 4];
      afb[3] = Qbu[(r0i + 8) * QS_STR + kd * 8 + t + 4];
      afs[0] = Qsu[r0i * QS_STR + kd * 8 + t];
      afs[1] = Qsu[(r0i + 8) * QS_STR + kd * 8 + t];
      afs[2] = Qsu[r0i * QS_STR + kd * 8 + t + 4];
      afs[3] = Qsu[(r0i + 8) * QS_STR + kd * 8 + t + 4];
#pragma unroll
      for (int nt = 0; nt < 2; nt++) {
        int krow = jb + nt * 8 + g;
        unsigned bfb[2], bfs[2];
        bfb[0] = Kbu[krow * KS_STR + kd * 8 + t];
        bfb[1] = Kbu[krow * KS_STR + kd * 8 + t + 4];
        bfs[0] = Ksu[krow * KS_STR + kd * 8 + t];
        bfs[1] = Ksu[krow * KS_STR + kd * 8 + t + 4];
        mma_tf32(sacc[nt], afb, bfb);
        mma_tf32(sacc[nt], afs, bfb);
        mma_tf32(sacc[nt], afb, bfs);
      }
    }

    // Mask invalid keys (final tile only)
    if (nk < 64) {
#pragma unroll
      for (int nt = 0; nt < 2; nt++) {
        int j0 = jb + nt * 8 + 2 * t;
        if (k0 + j0 >= M_) { sacc[nt][0] = -INFINITY; sacc[nt][2] = -INFINITY; }
        if (k0 + j0 + 1 >= M_) { sacc[nt][1] = -INFINITY; sacc[nt][3] = -INFINITY; }
      }
    }

    // --- Per-quarter row max, then cross-quarter combine via smem ---
    float mx0 = fmaxf(fmaxf(sacc[0][0], sacc[0][1]), fmaxf(sacc[1][0], sacc[1][1]));
    float mx1 = fmaxf(fmaxf(sacc[0][2], sacc[0][3]), fmaxf(sacc[1][2], sacc[1][3]));
#pragma unroll
    for (int off = 1; off < 4; off <<= 1) {
      mx0 = fmaxf(mx0, __shfl_xor_sync(0xffffffffu, mx0, off));
      mx1 = fmaxf(mx1, __shfl_xor_sync(0xffffffffu, mx1, off));
    }
    if (t == 0) {
      redm[quar * 64 + r0i] = mx0;
      redm[quar * 64 + r0i + 8] = mx1;
    }
    __syncthreads();
#pragma unroll
    for (int q = 0; q < 4; q++) {
      if (q != quar) {
        mx0 = fmaxf(mx0, redm[q * 64 + r0i]);
        mx1 = fmaxf(mx1, redm[q * 64 + r0i + 8]);
      }
    }

    float mn0 = fmaxf(m0v, mx0), mn1 = fmaxf(m1v, mx1);
    float sc0 = __expf(m0v - mn0), sc1 = __expf(m1v - mn1);
    m0v = mn0; m1v = mn1;

    float s0 = 0.0f, s1 = 0.0f;
#pragma unroll
    for (int nt = 0; nt < 2; nt++) {
      float e0 = __expf(sacc[nt][0] - mn0);
      float e1 = __expf(sacc[nt][1] - mn0);
      float e2 = __expf(sacc[nt][2] - mn1);
      float e3 = __expf(sacc[nt][3] - mn1);
      s0 += e0 + e1;
      s1 += e2 + e3;
      int col = jb + nt * 8 + 2 * t;
      Ps[r0i * PS_STR + col] = to_tf32(e0);
      Ps[r0i * PS_STR + col + 1] = to_tf32(e1);
      Ps[(r0i + 8) * PS_STR + col] = to_tf32(e2);
      Ps[(r0i + 8) * PS_STR + col + 1] = to_tf32(e3);
    }
#pragma unroll
    for (int off = 1; off < 4; off <<= 1) {
      s0 += __shfl_xor_sync(0xffffffffu, s0, off);
      s1 += __shfl_xor_sync(0xffffffffu, s1, off);
    }
    l0v = l0v * sc0 + s0;  // per-quarter partial (sc identical across quarters)
    l1v = l1v * sc1 + s1;
#pragma unroll
    for (int dt = 0; dt < 16; dt++) {
      Oa[dt][0] *= sc0; Oa[dt][1] *= sc0;
      Oa[dt][2] *= sc1; Oa[dt][3] *= sc1;
    }
    __syncwarp();  // own-quarter P strip is warp-private

    // --- O += P . V over own key quarter (2 kk of 8 keys) ---
#pragma unroll
    for (int kk = 0; kk < 2; kk++) {
      unsigned af[4];
      af[0] = Pu[r0i * PS_STR + jb + kk * 8 + t];
      af[1] = Pu[(r0i + 8) * PS_STR + jb + kk * 8 + t];
      af[2] = Pu[r0i * PS_STR + jb + kk * 8 + t + 4];
      af[3] = Pu[(r0i + 8) * PS_STR + jb + kk * 8 + t + 4];
#pragma unroll
      for (int dt = 0; dt < 16; dt++) {
        unsigned bf[2];
        bf[0] = Vu[(jb + kk * 8 + t) * VS_STR + dt * 8 + g];
        bf[1] = Vu[(jb + kk * 8 + t + 4) * VS_STR + dt * 8 + g];
        mma_tf32(Oa[dt], af, bf);
      }
    }
  }

  // --- Merge quarters: 1-3 export O partials + l; quarter 0 sums, stores ---
  __syncthreads();  // all warps done with Kb/Ks/Vs mma reads
  if (quar != 0) {
    float* Ored = (quar == 1) ? Kb : (quar == 2) ? Ks : Vs;
    if (t == 0) {
      lred[(quar - 1) * 64 + r0i] = l0v;
      lred[(quar - 1) * 64 + r0i + 8] = l1v;
    }
#pragma unroll
    for (int dt = 0; dt < 16; dt++) {
      *(float2*)(Ored + r0i * OR_STR + dt * 8 + 2 * t) =
          make_float2(Oa[dt][0], Oa[dt][1]);
      *(float2*)(Ored + (r0i + 8) * OR_STR + dt * 8 + 2 * t) =
          make_float2(Oa[dt][2], Oa[dt][3]);
    }
  }
  __syncthreads();
  if (quar == 0) {
    float lt0 = l0v + lred[r0i] + lred[64 + r0i] + lred[128 + r0i];
    float lt1 = l1v + lred[r0i + 8] + lred[64 + r0i + 8] + lred[128 + r0i + 8];
    float inv0 = 1.0f / lt0, inv1 = 1.0f / lt1;
    float* yb = g_y + (size_t)b * N_ * D_;
#pragma unroll
    for (int dt = 0; dt < 16; dt++) {
      int col = dt * 8 + 2 * t;
      float2 a0 = *(float2*)(Kb + r0i * OR_STR + col);
      float2 b0 = *(float2*)(Ks + r0i * OR_STR + col);
      float2 c0 = *(float2*)(Vs + r0i * OR_STR + col);
      float2 a1 = *(float2*)(Kb + (r0i + 8) * OR_STR + col);
      float2 b1 = *(float2*)(Ks + (r0i + 8) * OR_STR + col);
      float2 c1 = *(float2*)(Vs + (r0i + 8) * OR_STR + col);
      *(float2*)(yb + (size_t)(q0 + r0i) * D_ + col) =
          make_float2((Oa[dt][0] + a0.x + b0.x + c0.x) * inv0,
                      (Oa[dt][1] + a0.y + b0.y + c0.y) * inv0);
      *(float2*)(yb + (size_t)(q0 + r0i + 8) * D_ + col) =
          make_float2((Oa[dt][2] + a1.x + b1.x + c1.x) * inv1,
                      (Oa[dt][3] + a1.y + b1.y + c1.y) * inv1);
    }
  }
}

// ---------------------------------------------------------------------------
// Kernel 3: z = x + y @ Wf.  M=16384, K=128, Nout=256.
// ---------------------------------------------------------------------------
__global__ __launch_bounds__(256) void zout_kernel(const float* __restrict__ x,
                                                   const float* __restrict__ Wf,
                                                   float* __restrict__ z) {
  __shared__ float As[64 * 36];
  __shared__ float Bs[64 * 36];

  const int m0 = blockIdx.y * 64;
  const int n0 = blockIdx.x * 64;
  const int tid = threadIdx.x;
  const int tx = tid & 15, ty = tid >> 4;

  float acc[4][4];
#pragma unroll
  for (int r = 0; r < 4; r++)
#pragma unroll
    for (int c = 0; c < 4; c++) acc[r][c] = 0.0f;

  for (int k0 = 0; k0 < D_; k0 += 32) {
    {
      int row = tid >> 3;
      int c4 = tid & 7;
      float4 v0 = *(const float4*)(g_y + (size_t)(m0 + row) * D_ + k0 + c4 * 4);
      *(float4*)(As + row * 36 + c4 * 4) = v0;
      float4 v1 = *(const float4*)(g_y + (size_t)(m0 + row + 32) * D_ + k0 + c4 * 4);
      *(float4*)(As + (row + 32) * 36 + c4 * 4) = v1;
    }
    {
      int kr = tid >> 4;
      int c4 = tid & 15;
      float4 v0 = *(const float4*)(Wf + (size_t)(k0 + kr) * C_ + n0 + c4 * 4);
      Bs[(c4 * 4 + 0) * 36 + kr] = v0.x;
      Bs[(c4 * 4 + 1) * 36 + kr] = v0.y;
      Bs[(c4 * 4 + 2) * 36 + kr] = v0.z;
      Bs[(c4 * 4 + 3) * 36 + kr] = v0.w;
      float4 v1 = *(const float4*)(Wf + (size_t)(k0 + kr + 16) * C_ + n0 + c4 * 4);
      Bs[(c4 * 4 + 0) * 36 + kr + 16] = v1.x;
      Bs[(c4 * 4 + 1) * 36 + kr + 16] = v1.y;
      Bs[(c4 * 4 + 2) * 36 + kr + 16] = v1.z;
      Bs[(c4 * 4 + 3) * 36 + kr + 16] = v1.w;
    }
    __syncthreads();
#pragma unroll
    for (int kk = 0; kk < 32; kk += 4) {
      float4 a[4], b[4];
#pragma unroll
      for (int r = 0; r < 4; r++) a[r] = *(float4*)(As + (ty * 4 + r) * 36 + kk);
#pragma unroll
      for (int c = 0; c < 4; c++) b[c] = *(float4*)(Bs + (tx + 16 * c) * 36 + kk);
#pragma unroll
      for (int r = 0; r < 4; r++)
#pragma unroll
        for (int c = 0; c < 4; c++)
          acc[r][c] += a[r].x * b[c].x + a[r].y * b[c].y + a[r].z * b[c].z + a[r].w * b[c].w;
    }
    __syncthreads();
  }
#pragma unroll
  for (int r = 0; r < 4; r++)
#pragma unroll
    for (int c = 0; c < 4; c++) {
      size_t idx = (size_t)(m0 + ty * 4 + r) * C_ + n0 + tx + 16 * c;
      z[idx] = x[idx] + acc[r][c];
    }
}

// ---------------------------------------------------------------------------
extern "C" void kernel_launch(void* const* d_in, const int* in_sizes, int n_in,
                              void* d_out, int out_size) {
  (void)in_sizes; (void)n_in; (void)out_size;
  const float* x = (const float*)d_in[0];
  const float* Wt = (const float*)d_in[1];
  const float* Wp = (const float*)d_in[2];
  const float* Wg = (const float*)d_in[3];
  const float* Wf = (const float*)d_in[4];
  float* z = (float*)d_out;

  proj_kernel<<<dim3(D_ / 64, (B_ * N_) / 64, 3), 256>>>(x, Wt, Wp, Wg);

  size_t smem =
      (size_t)(64 * (4 * QS_STR + VS_STR + PS_STR) + 256 + 192) * sizeof(float);
  cudaFuncSetAttribute(attn_kernel, cudaFuncAttributeMaxDynamicSharedMemorySize,
                       (int)smem);
  attn_kernel<<<dim3(N_ / 64, B_), 512, smem>>>();

  zout_kernel<<<dim3(C_ / 64, (B_ * N_) / 64), 256>>>(x, Wf, z);
}